// round 1
// baseline (speedup 1.0000x reference)
#include <cuda_runtime.h>
#include <math.h>

#define CDIM   128
#define LTOK   54      // 6*9 target tokens per batch
#define NTOK   8       // query tokens
#define NCOLS  192     // 64 dot-logit cols + 128 V cols
#define LN_EPS 1e-5f

// Precomputed fused weights (written by precompute kernel, read by main kernel)
__device__ float g_Wc[CDIM * NCOLS];   // [k][c]: c<64 -> A (scaled qK fold), c>=64 -> Wv
__device__ float g_dc[64];             // per-(tok,head) dot constant from bk

// ---------------- packed f32x2 helpers ----------------
__device__ __forceinline__ unsigned long long pack2(float lo, float hi) {
    unsigned long long r;
    asm("mov.b64 %0, {%1, %2};" : "=l"(r) : "f"(lo), "f"(hi));
    return r;
}
__device__ __forceinline__ void unpack2(unsigned long long v, float& lo, float& hi) {
    asm("mov.b64 {%0, %1}, %2;" : "=f"(lo), "=f"(hi) : "l"(v));
}
__device__ __forceinline__ void ffma2(unsigned long long& d, unsigned long long a, unsigned long long b) {
    asm("fma.rn.f32x2 %0, %1, %2, %0;" : "+l"(d) : "l"(a), "l"(b));
}

__device__ __forceinline__ float warp_sum(float v) {
    v += __shfl_xor_sync(0xffffffffu, v, 16);
    v += __shfl_xor_sync(0xffffffffu, v, 8);
    v += __shfl_xor_sync(0xffffffffu, v, 4);
    v += __shfl_xor_sync(0xffffffffu, v, 2);
    v += __shfl_xor_sync(0xffffffffu, v, 1);
    return v;
}

// ---------------- precompute: LN(query) -> q -> fold into A, dc; copy Wv ----------------
__global__ void precompute_kernel(
    const float* __restrict__ query,
    const float* __restrict__ ln1_g, const float* __restrict__ ln1_b,
    const float* __restrict__ Wq, const float* __restrict__ bq,
    const float* __restrict__ Wk, const float* __restrict__ bk,
    const float* __restrict__ Wv)
{
    __shared__ float s_qn[NTOK * CDIM];
    __shared__ float s_q[NTOK * CDIM];
    const int tid = threadIdx.x;       // 256 threads
    const int warp = tid >> 5, lane = tid & 31;

    // LayerNorm of the 8 query rows: one warp per row
    if (warp < NTOK) {
        const int r = warp;
        float4 xv = *(const float4*)&query[r * CDIM + lane * 4];
        float s1 = xv.x + xv.y + xv.z + xv.w;
        float s2 = xv.x * xv.x + xv.y * xv.y + xv.z * xv.z + xv.w * xv.w;
        s1 = warp_sum(s1);
        s2 = warp_sum(s2);
        float m = s1 * (1.0f / 128.0f);
        float var = s2 * (1.0f / 128.0f) - m * m;
        float rs = rsqrtf(var + LN_EPS);
        float4 g = *(const float4*)&ln1_g[lane * 4];
        float4 be = *(const float4*)&ln1_b[lane * 4];
        float4 o;
        o.x = (xv.x - m) * rs * g.x + be.x;
        o.y = (xv.y - m) * rs * g.y + be.y;
        o.z = (xv.z - m) * rs * g.z + be.z;
        o.w = (xv.w - m) * rs * g.w + be.w;
        *(float4*)&s_qn[r * CDIM + lane * 4] = o;
    }
    __syncthreads();

    // q = qn @ Wq + bq  (8 x 128 outputs)
    for (int idx = tid; idx < NTOK * CDIM; idx += 256) {
        int t = idx >> 7, o = idx & 127;
        float acc = bq[o];
        for (int c = 0; c < CDIM; c++) acc += s_qn[t * CDIM + c] * Wq[c * CDIM + o];
        s_q[idx] = acc;
    }
    __syncthreads();

    // A[c][tok*8+h] = 0.25 * sum_j q[tok][h*16+j] * Wk[c][h*16+j]   (scale = (128/8)^-0.5 = 0.25)
    for (int idx = tid; idx < CDIM * 64; idx += 256) {
        int c = idx >> 6, th = idx & 63;
        int tok = th >> 3, h = th & 7;
        float acc = 0.0f;
        for (int j = 0; j < 16; j++)
            acc += s_q[tok * CDIM + h * 16 + j] * Wk[c * CDIM + h * 16 + j];
        g_Wc[c * NCOLS + th] = 0.25f * acc;
    }
    // V weight copy into combined matrix
    for (int idx = tid; idx < CDIM * CDIM; idx += 256) {
        int c = idx >> 7, o = idx & 127;
        g_Wc[c * NCOLS + 64 + o] = Wv[c * CDIM + o];
    }
    // dot constants from bk
    if (tid < 64) {
        int tok = tid >> 3, h = tid & 7;
        float acc = 0.0f;
        for (int j = 0; j < 16; j++)
            acc += s_q[tok * CDIM + h * 16 + j] * bk[h * 16 + j];
        g_dc[tid] = 0.25f * acc;
    }
}

// ---------------- fused main kernel: one block per batch ----------------
// smem layout (floats)
#define OFF_TGT  0
#define OFF_V    (LTOK * CDIM)                 // 6912
#define OFF_DOTS (OFF_V + LTOK * CDIM)         // 13824
#define OFF_ATTN (OFF_DOTS + LTOK * 64)        // 17280
#define OFF_X    (OFF_ATTN + NTOK * CDIM)      // 18304
#define OFF_LN   (OFF_X + NTOK * CDIM)         // 19328
#define OFF_F    (OFF_LN + NTOK * CDIM)        // 20352
#define SMEM_FLOATS (OFF_F + NTOK * CDIM)      // 21376
#define SMEM_BYTES  (SMEM_FLOATS * 4)          // 85504

__global__ __launch_bounds__(192, 2) void fused_main_kernel(
    const float* __restrict__ tgt,
    const float* __restrict__ query,
    const float* __restrict__ ln2_g, const float* __restrict__ ln2_b,
    const float* __restrict__ bv,
    const float* __restrict__ Wp, const float* __restrict__ bp,
    const float* __restrict__ Wf1, const float* __restrict__ bf1,
    const float* __restrict__ Wf2, const float* __restrict__ bf2,
    float* __restrict__ out)
{
    extern __shared__ float sm[];
    float* s_tgt  = sm + OFF_TGT;
    float* s_v    = sm + OFF_V;
    float* s_dots = sm + OFF_DOTS;
    float* s_attn = sm + OFF_ATTN;
    float* s_x    = sm + OFF_X;
    float* s_ln   = sm + OFF_LN;
    float* s_f    = sm + OFF_F;

    const int tid = threadIdx.x;   // 192
    const int b = blockIdx.x;

    // ---- Phase 0: load tgt[b] (54x128 fp32 = 27 KB) ----
    {
        const float4* gt = (const float4*)(tgt + (size_t)b * (LTOK * CDIM));
        float4* st = (float4*)s_tgt;
        #pragma unroll
        for (int i = 0; i < (LTOK * CDIM / 4) / 192; i++)
            st[tid + i * 192] = gt[tid + i * 192];
    }
    __syncthreads();

    // ---- Phase 1: GEMM1  [54,128] @ [128,192] via packed f32x2 FMA ----
    {
        const int c = tid;
        unsigned long long acc2[LTOK];
        #pragma unroll
        for (int l = 0; l < LTOK; l++) acc2[l] = 0ULL;

        #pragma unroll 1
        for (int k0 = 0; k0 < CDIM; k0 += 8) {
            float w0 = g_Wc[(k0 + 0) * NCOLS + c];
            float w1 = g_Wc[(k0 + 1) * NCOLS + c];
            float w2 = g_Wc[(k0 + 2) * NCOLS + c];
            float w3 = g_Wc[(k0 + 3) * NCOLS + c];
            float w4 = g_Wc[(k0 + 4) * NCOLS + c];
            float w5 = g_Wc[(k0 + 5) * NCOLS + c];
            float w6 = g_Wc[(k0 + 6) * NCOLS + c];
            float w7 = g_Wc[(k0 + 7) * NCOLS + c];
            unsigned long long wp0 = pack2(w0, w1);
            unsigned long long wp1 = pack2(w2, w3);
            unsigned long long wp2 = pack2(w4, w5);
            unsigned long long wp3 = pack2(w6, w7);
            #pragma unroll
            for (int l = 0; l < LTOK; l++) {
                const ulonglong2* p = (const ulonglong2*)(s_tgt + l * CDIM + k0);
                ulonglong2 ta = p[0];   // floats k0..k0+3
                ulonglong2 tb = p[1];   // floats k0+4..k0+7
                ffma2(acc2[l], ta.x, wp0);
                ffma2(acc2[l], ta.y, wp1);
                ffma2(acc2[l], tb.x, wp2);
                ffma2(acc2[l], tb.y, wp3);
            }
        }

        if (c < 64) {
            float dc = g_dc[c];
            #pragma unroll
            for (int l = 0; l < LTOK; l++) {
                float lo, hi; unpack2(acc2[l], lo, hi);
                s_dots[l * 64 + c] = lo + hi + dc;
            }
        } else {
            float bvv = bv[c - 64];
            #pragma unroll
            for (int l = 0; l < LTOK; l++) {
                float lo, hi; unpack2(acc2[l], lo, hi);
                s_v[l * CDIM + (c - 64)] = lo + hi + bvv;
            }
        }
    }
    __syncthreads();

    // ---- Phase 2: region softmax + attention-weighted V  (64 (tok,head) tasks) ----
    if (tid < 64) {
        const int tok = tid >> 3, h = tid & 7;
        const int ridx = (tok < 2) ? tok : (tok - 2);
        const int hb = ridx / 3, wb = ridx % 3;
        const int l0 = hb * 3 * 9 + wb * 3;
        int ls[9];
        #pragma unroll
        for (int d = 0; d < 9; d++) ls[d] = l0 + (d / 3) * 9 + (d % 3);

        float dv[9];
        float mx = -1e30f;
        #pragma unroll
        for (int d = 0; d < 9; d++) {
            dv[d] = s_dots[ls[d] * 64 + tid];   // column index == tok*8+h == tid
            mx = fmaxf(mx, dv[d]);
        }
        float ssum = 0.0f;
        #pragma unroll
        for (int d = 0; d < 9; d++) {
            dv[d] = __expf(dv[d] - mx);
            ssum += dv[d];
        }
        const float inv = 1.0f / ssum;
        const int vbase = h * 16;
        #pragma unroll
        for (int jj = 0; jj < 4; jj++) {
            float4 acc = make_float4(0.f, 0.f, 0.f, 0.f);
            #pragma unroll
            for (int d = 0; d < 9; d++) {
                float4 vv = *(const float4*)&s_v[ls[d] * CDIM + vbase + jj * 4];
                acc.x += dv[d] * vv.x; acc.y += dv[d] * vv.y;
                acc.z += dv[d] * vv.z; acc.w += dv[d] * vv.w;
            }
            acc.x *= inv; acc.y *= inv; acc.z *= inv; acc.w *= inv;
            *(float4*)&s_attn[tok * CDIM + vbase + jj * 4] = acc;
        }
    }
    __syncthreads();

    // ---- Phase 3: x = query + attn @ Wp + bp ----
    if (tid < CDIM) {
        const int cc = tid;
        float acc[NTOK];
        const float bpc = bp[cc];
        #pragma unroll
        for (int r = 0; r < NTOK; r++) acc[r] = bpc;
        #pragma unroll 4
        for (int k0 = 0; k0 < CDIM; k0 += 4) {
            float w0 = Wp[(k0 + 0) * CDIM + cc];
            float w1 = Wp[(k0 + 1) * CDIM + cc];
            float w2 = Wp[(k0 + 2) * CDIM + cc];
            float w3 = Wp[(k0 + 3) * CDIM + cc];
            #pragma unroll
            for (int r = 0; r < NTOK; r++) {
                float4 t = *(const float4*)&s_attn[r * CDIM + k0];
                acc[r] += t.x * w0 + t.y * w1 + t.z * w2 + t.w * w3;
            }
        }
        #pragma unroll
        for (int r = 0; r < NTOK; r++)
            s_x[r * CDIM + cc] = acc[r] + query[r * CDIM + cc];
    }
    __syncthreads();

    // ---- Phase 4: LN2 over x rows ----
    {
        const int warp = tid >> 5, lane = tid & 31;
        for (int r = warp; r < NTOK; r += 6) {
            float4 xv = *(const float4*)&s_x[r * CDIM + lane * 4];
            float s1 = xv.x + xv.y + xv.z + xv.w;
            float s2 = xv.x * xv.x + xv.y * xv.y + xv.z * xv.z + xv.w * xv.w;
            s1 = warp_sum(s1);
            s2 = warp_sum(s2);
            float m = s1 * (1.0f / 128.0f);
            float var = s2 * (1.0f / 128.0f) - m * m;
            float rs = rsqrtf(var + LN_EPS);
            float4 g = *(const float4*)&ln2_g[lane * 4];
            float4 be = *(const float4*)&ln2_b[lane * 4];
            float4 o;
            o.x = (xv.x - m) * rs * g.x + be.x;
            o.y = (xv.y - m) * rs * g.y + be.y;
            o.z = (xv.z - m) * rs * g.z + be.z;
            o.w = (xv.w - m) * rs * g.w + be.w;
            *(float4*)&s_ln[r * CDIM + lane * 4] = o;
        }
    }
    __syncthreads();

    // ---- Phase 5: f = gelu(ln @ Wf1 + bf1)  (exact erf gelu) ----
    if (tid < CDIM) {
        const int cc = tid;
        float acc[NTOK];
        const float b1 = bf1[cc];
        #pragma unroll
        for (int r = 0; r < NTOK; r++) acc[r] = b1;
        #pragma unroll 4
        for (int k0 = 0; k0 < CDIM; k0 += 4) {
            float w0 = Wf1[(k0 + 0) * CDIM + cc];
            float w1 = Wf1[(k0 + 1) * CDIM + cc];
            float w2 = Wf1[(k0 + 2) * CDIM + cc];
            float w3 = Wf1[(k0 + 3) * CDIM + cc];
            #pragma unroll
            for (int r = 0; r < NTOK; r++) {
                float4 t = *(const float4*)&s_ln[r * CDIM + k0];
                acc[r] += t.x * w0 + t.y * w1 + t.z * w2 + t.w * w3;
            }
        }
        #pragma unroll
        for (int r = 0; r < NTOK; r++) {
            float v = acc[r];
            s_f[r * CDIM + cc] = 0.5f * v * (1.0f + erff(v * 0.70710678118654752f));
        }
    }
    __syncthreads();

    // ---- Phase 6: out = x + (f @ Wf2 + bf2) ----
    if (tid < CDIM) {
        const int cc = tid;
        float acc[NTOK];
        const float b2 = bf2[cc];
        #pragma unroll
        for (int r = 0; r < NTOK; r++) acc[r] = b2;
        #pragma unroll 4
        for (int k0 = 0; k0 < CDIM; k0 += 4) {
            float w0 = Wf2[(k0 + 0) * CDIM + cc];
            float w1 = Wf2[(k0 + 1) * CDIM + cc];
            float w2 = Wf2[(k0 + 2) * CDIM + cc];
            float w3 = Wf2[(k0 + 3) * CDIM + cc];
            #pragma unroll
            for (int r = 0; r < NTOK; r++) {
                float4 t = *(const float4*)&s_f[r * CDIM + k0];
                acc[r] += t.x * w0 + t.y * w1 + t.z * w2 + t.w * w3;
            }
        }
        float* ob = out + (size_t)b * (NTOK * CDIM);
        #pragma unroll
        for (int r = 0; r < NTOK; r++)
            ob[r * CDIM + cc] = s_x[r * CDIM + cc] + acc[r];
    }
}

// ---------------- launch ----------------
extern "C" void kernel_launch(void* const* d_in, const int* in_sizes, int n_in,
                              void* d_out, int out_size)
{
    const float* query = (const float*)d_in[0];
    const float* tgt   = (const float*)d_in[1];
    const float* ln1_g = (const float*)d_in[2];
    const float* ln1_b = (const float*)d_in[3];
    const float* ln2_g = (const float*)d_in[4];
    const float* ln2_b = (const float*)d_in[5];
    const float* Wq    = (const float*)d_in[6];
    const float* bq    = (const float*)d_in[7];
    const float* Wk    = (const float*)d_in[8];
    const float* bk    = (const float*)d_in[9];
    const float* Wv    = (const float*)d_in[10];
    const float* bv    = (const float*)d_in[11];
    const float* Wp    = (const float*)d_in[12];
    const float* bp    = (const float*)d_in[13];
    const float* Wf1   = (const float*)d_in[14];
    const float* bf1   = (const float*)d_in[15];
    const float* Wf2   = (const float*)d_in[16];
    const float* bf2   = (const float*)d_in[17];
    float* out = (float*)d_out;

    const int B = in_sizes[1] / (LTOK * CDIM);

    cudaFuncSetAttribute(fused_main_kernel,
                         cudaFuncAttributeMaxDynamicSharedMemorySize, SMEM_BYTES);

    precompute_kernel<<<1, 256>>>(query, ln1_g, ln1_b, Wq, bq, Wk, bk, Wv);
    fused_main_kernel<<<B, 192, SMEM_BYTES>>>(
        tgt, query, ln2_g, ln2_b, bv, Wp, bp, Wf1, bf1, Wf2, bf2, out);
}

// round 2
// speedup vs baseline: 1.9555x; 1.9555x over previous
#include <cuda_runtime.h>
#include <math.h>

#define CDIM   128
#define LTOK   54
#define NTOK   8
#define LN_EPS 1e-5f
#define PADA   132     // padded row stride (floats) for mma A tiles
#define MAXB   8192

// ---------------- device globals (scratch + precomputed frag-ordered weights) ----------------
__device__ float g_x[(size_t)MAXB * NTOK * CDIM];   // 32MB scratch: x after attention+proj
__device__ float g_WcB [16 * 24 * 64];   // combined [A_fold | Wv] in B-fragment order, tf32
__device__ float g_WpB [16 * 16 * 64];   // Wp  frag order, tf32
__device__ float g_Wf1B[16 * 16 * 64];   // Wf1 frag order, tf32
__device__ float g_Wf2B[16 * 16 * 64];   // Wf2 frag order, tf32

// ---------------- helpers ----------------
__device__ __forceinline__ unsigned f2tf32(float f) {
    unsigned u;
    asm("cvt.rna.tf32.f32 %0, %1;" : "=r"(u) : "f"(f));
    return u;
}

__device__ __forceinline__ void mma_tf32(float* c, const unsigned* a, unsigned b0, unsigned b1) {
    asm volatile(
        "mma.sync.aligned.m16n8k8.row.col.f32.tf32.tf32.f32 "
        "{%0,%1,%2,%3},{%4,%5,%6,%7},{%8,%9},{%0,%1,%2,%3};"
        : "+f"(c[0]), "+f"(c[1]), "+f"(c[2]), "+f"(c[3])
        : "r"(a[0]), "r"(a[1]), "r"(a[2]), "r"(a[3]), "r"(b0), "r"(b1));
}

__device__ __forceinline__ float warp_sum(float v) {
    v += __shfl_xor_sync(0xffffffffu, v, 16);
    v += __shfl_xor_sync(0xffffffffu, v, 8);
    v += __shfl_xor_sync(0xffffffffu, v, 4);
    v += __shfl_xor_sync(0xffffffffu, v, 2);
    v += __shfl_xor_sync(0xffffffffu, v, 1);
    return v;
}

// ---------------- precompute: LN1 -> q -> fold into A_fold; weights to frag order ----------------
__global__ void precompute_kernel(
    const float* __restrict__ query,
    const float* __restrict__ ln1_g, const float* __restrict__ ln1_b,
    const float* __restrict__ Wq, const float* __restrict__ bq,
    const float* __restrict__ Wk,
    const float* __restrict__ Wv,
    const float* __restrict__ Wp,
    const float* __restrict__ Wf1,
    const float* __restrict__ Wf2)
{
    __shared__ float s_qn[NTOK * CDIM];
    __shared__ float s_q[NTOK * CDIM];
    const int tid = threadIdx.x;   // 256
    const int warp = tid >> 5, lane = tid & 31;

    if (warp < NTOK) {
        const int r = warp;
        float4 xv = *(const float4*)&query[r * CDIM + lane * 4];
        float s1 = xv.x + xv.y + xv.z + xv.w;
        float s2 = xv.x * xv.x + xv.y * xv.y + xv.z * xv.z + xv.w * xv.w;
        s1 = warp_sum(s1);
        s2 = warp_sum(s2);
        float m = s1 * (1.0f / 128.0f);
        float var = s2 * (1.0f / 128.0f) - m * m;
        float rs = rsqrtf(var + LN_EPS);
        float4 g = *(const float4*)&ln1_g[lane * 4];
        float4 be = *(const float4*)&ln1_b[lane * 4];
        float4 o;
        o.x = (xv.x - m) * rs * g.x + be.x;
        o.y = (xv.y - m) * rs * g.y + be.y;
        o.z = (xv.z - m) * rs * g.z + be.z;
        o.w = (xv.w - m) * rs * g.w + be.w;
        *(float4*)&s_qn[r * CDIM + lane * 4] = o;
    }
    __syncthreads();

    for (int idx = tid; idx < NTOK * CDIM; idx += 256) {
        int t = idx >> 7, o = idx & 127;
        float acc = bq[o];
        for (int c = 0; c < CDIM; c++) acc += s_qn[t * CDIM + c] * Wq[c * CDIM + o];
        s_q[idx] = acc;
    }
    __syncthreads();

    // g_WcB: combined B frag order. idx = ((ks*24+nt)*32+lane)*2 + j
    for (int idx = tid; idx < 16 * 24 * 64; idx += 256) {
        int j = idx & 1;
        int pair = idx >> 1;
        int ln = pair & 31;
        int q2 = pair >> 5;
        int nt = q2 % 24;
        int ks = q2 / 24;
        int k = ks * 8 + (ln & 3) + 4 * j;
        int c = nt * 8 + (ln >> 2);
        float val;
        if (c < 64) {
            int tok = c >> 3, h = c & 7;
            float acc = 0.0f;
            for (int jj = 0; jj < 16; jj++)
                acc += s_q[tok * CDIM + h * 16 + jj] * Wk[k * CDIM + h * 16 + jj];
            val = 0.25f * acc;   // scale (128/8)^-0.5; bk contribution cancels in softmax
        } else {
            val = Wv[k * CDIM + (c - 64)];
        }
        g_WcB[idx] = __uint_as_float(f2tf32(val));
    }

    // Wp / Wf1 / Wf2 frag order: idx = ((ks*16+nt)*32+lane)*2 + j
    for (int idx = tid; idx < 16 * 16 * 64; idx += 256) {
        int j = idx & 1;
        int pair = idx >> 1;
        int ln = pair & 31;
        int q2 = pair >> 5;
        int nt = q2 & 15;
        int ks = q2 >> 4;
        int k = ks * 8 + (ln & 3) + 4 * j;
        int c = nt * 8 + (ln >> 2);
        g_WpB [idx] = __uint_as_float(f2tf32(Wp [k * CDIM + c]));
        g_Wf1B[idx] = __uint_as_float(f2tf32(Wf1[k * CDIM + c]));
        g_Wf2B[idx] = __uint_as_float(f2tf32(Wf2[k * CDIM + c]));
    }
}

// ---------------- attention kernel: 2 batches per block, 256 threads ----------------
// smem: sA  [2*64][132]  tgt(tf32) then reused for V(fp32)   16896 floats
//       sD  [2*54][68]   dots fp32                            7344 floats
//       sAt [16][132]    attn tf32                            2112 floats
#define SM_A_FLOATS   (2 * 64 * PADA)
#define SM_D_FLOATS   (2 * 54 * 68)
#define SM_AT_FLOATS  (16 * PADA)
#define SM_ATTN_TOTAL (SM_A_FLOATS + SM_D_FLOATS + SM_AT_FLOATS)
#define SM_ATTN_BYTES (SM_ATTN_TOTAL * 4)

__global__ __launch_bounds__(256, 2) void attn_kernel(
    const float* __restrict__ tgt,
    const float* __restrict__ query,
    const float* __restrict__ bv,
    const float* __restrict__ bp)
{
    extern __shared__ float sm[];
    float* sA  = sm;
    float* sD  = sm + SM_A_FLOATS;
    float* sAt = sm + SM_A_FLOATS + SM_D_FLOATS;

    const int tid = threadIdx.x;
    const int w = tid >> 5, lane = tid & 31;
    const int g = lane >> 2, t = lane & 3;
    const int b0 = blockIdx.x * 2;

    // ---- stage tgt (2 batches), round to tf32 ----
    {
        const float4* gt = (const float4*)(tgt + (size_t)b0 * (LTOK * CDIM));
        for (int i = tid; i < 2 * LTOK * 32; i += 256) {
            int row = i >> 5, c4 = i & 31;
            float4 v = __ldg(gt + i);
            int bb = (row >= LTOK) ? 1 : 0;
            int r = row - bb * LTOK;
            uint4 u;
            u.x = f2tf32(v.x); u.y = f2tf32(v.y); u.z = f2tf32(v.z); u.w = f2tf32(v.w);
            *(uint4*)&sA[(bb * 64 + r) * PADA + c4 * 4] = u;
        }
    }
    __syncthreads();

    // ---- GEMM1: [108(pad128), 128] @ [128, 192] -> dots(64) | V(128) ----
    // warp grid: mg = w>>2 (batch / 4 m-tiles), ng = w&3 (6 n-tiles each)
    {
        const int mg = w >> 2, ng = w & 3;
        float C[4][6][4];
        #pragma unroll
        for (int m = 0; m < 4; m++)
            #pragma unroll
            for (int n = 0; n < 6; n++)
                #pragma unroll
                for (int q = 0; q < 4; q++) C[m][n][q] = 0.0f;

        const unsigned* sAu = (const unsigned*)sA;
        const uint2* WB = (const uint2*)g_WcB;

        #pragma unroll 1
        for (int ks = 0; ks < 16; ks++) {
            unsigned A[4][4];
            #pragma unroll
            for (int m = 0; m < 4; m++) {
                const unsigned* pa = sAu + (mg * 64 + m * 16 + g) * PADA + ks * 8 + t;
                A[m][0] = pa[0];
                A[m][1] = pa[8 * PADA];
                A[m][2] = pa[4];
                A[m][3] = pa[8 * PADA + 4];
            }
            #pragma unroll
            for (int n = 0; n < 6; n++) {
                uint2 b = __ldg(WB + ((ks * 24 + ng * 6 + n) * 32 + lane));
                #pragma unroll
                for (int m = 0; m < 4; m++)
                    mma_tf32(C[m][n], A[m], b.x, b.y);
            }
        }
        __syncthreads();   // all A reads done before V overwrites sA

        // write C frags: cols<64 -> dots, cols>=64 -> V (into sA region, fp32)
        #pragma unroll
        for (int m = 0; m < 4; m++) {
            const int bb = mg;
            const int r1 = m * 16 + g;
            #pragma unroll
            for (int n = 0; n < 6; n++) {
                int nt = ng * 6 + n;
                int c0 = nt * 8 + 2 * t;
                if (nt < 8) {
                    float* d0 = sD + (bb * LTOK + r1) * 68 + c0;
                    if (r1 < LTOK)     *(float2*)d0            = make_float2(C[m][n][0], C[m][n][1]);
                    if (r1 + 8 < LTOK) *(float2*)(d0 + 8 * 68) = make_float2(C[m][n][2], C[m][n][3]);
                } else {
                    int c = c0 - 64;
                    float* v0 = sA + (bb * 64 + r1) * PADA + c;
                    if (r1 < LTOK)     *(float2*)v0              = make_float2(C[m][n][0], C[m][n][1]);
                    if (r1 + 8 < LTOK) *(float2*)(v0 + 8 * PADA) = make_float2(C[m][n][2], C[m][n][3]);
                }
            }
        }
    }
    __syncthreads();

    // ---- softmax + AV (128 tasks: 2 batches x 8 tok x 8 heads) ----
    if (tid < 128) {
        const int bb = tid >> 6, th = tid & 63;
        const int tok = th >> 3, h = th & 7;
        const int ridx = (tok < 2) ? tok : (tok - 2);
        const int hb = ridx / 3, wb = ridx % 3;
        const int l0 = hb * 27 + wb * 3;
        int ls[9];
        #pragma unroll
        for (int d = 0; d < 9; d++) ls[d] = l0 + (d / 3) * 9 + (d % 3);

        float dv[9];
        float mx = -1e30f;
        #pragma unroll
        for (int d = 0; d < 9; d++) {
            dv[d] = sD[(bb * LTOK + ls[d]) * 68 + th];
            mx = fmaxf(mx, dv[d]);
        }
        float ssum = 0.0f;
        #pragma unroll
        for (int d = 0; d < 9; d++) {
            dv[d] = __expf(dv[d] - mx);
            ssum += dv[d];
        }
        const float inv = 1.0f / ssum;
        const int base = h * 16;
        #pragma unroll
        for (int jj = 0; jj < 4; jj++) {
            float4 acc = make_float4(0.f, 0.f, 0.f, 0.f);
            #pragma unroll
            for (int d = 0; d < 9; d++) {
                const float4 vv = *(const float4*)&sA[(bb * 64 + ls[d]) * PADA + base + jj * 4];
                acc.x += dv[d] * vv.x; acc.y += dv[d] * vv.y;
                acc.z += dv[d] * vv.z; acc.w += dv[d] * vv.w;
            }
            float4 bvv = __ldg((const float4*)(bv + base + jj * 4));
            uint4 u;
            u.x = f2tf32(acc.x * inv + bvv.x);
            u.y = f2tf32(acc.y * inv + bvv.y);
            u.z = f2tf32(acc.z * inv + bvv.z);
            u.w = f2tf32(acc.w * inv + bvv.w);
            *(uint4*)&sAt[(bb * 8 + tok) * PADA + base + jj * 4] = u;
        }
    }
    __syncthreads();

    // ---- proj: x = query + attn @ Wp + bp ; write to g_x ----
    {
        float Cp[2][4];
        #pragma unroll
        for (int n = 0; n < 2; n++)
            #pragma unroll
            for (int q = 0; q < 4; q++) Cp[n][q] = 0.0f;

        const unsigned* sau = (const unsigned*)sAt;
        const uint2* WPB = (const uint2*)g_WpB;

        #pragma unroll 1
        for (int ks = 0; ks < 16; ks++) {
            const unsigned* pa = sau + g * PADA + ks * 8 + t;
            unsigned A4[4];
            A4[0] = pa[0];
            A4[1] = pa[8 * PADA];
            A4[2] = pa[4];
            A4[3] = pa[8 * PADA + 4];
            #pragma unroll
            for (int n = 0; n < 2; n++) {
                uint2 b = __ldg(WPB + ((ks * 16 + w * 2 + n) * 32 + lane));
                mma_tf32(Cp[n], A4, b.x, b.y);
            }
        }

        #pragma unroll
        for (int n = 0; n < 2; n++) {
            const int c0 = (w * 2 + n) * 8 + 2 * t;
            const float bp0 = __ldg(bp + c0), bp1 = __ldg(bp + c0 + 1);
            const int r1 = g;          // (bb=0, tok=g)
            const int r2 = g + 8;      // (bb=1, tok=g)
            const float q0 = __ldg(query + (r1 & 7) * CDIM + c0);
            const float q1 = __ldg(query + (r1 & 7) * CDIM + c0 + 1);
            float2 x1 = make_float2(Cp[n][0] + bp0 + q0, Cp[n][1] + bp1 + q1);
            float2 x2 = make_float2(Cp[n][2] + bp0 + q0, Cp[n][3] + bp1 + q1);
            *(float2*)&g_x[((size_t)(b0 + (r1 >> 3)) * 8 + (r1 & 7)) * CDIM + c0] = x1;
            *(float2*)&g_x[((size_t)(b0 + (r2 >> 3)) * 8 + (r2 & 7)) * CDIM + c0] = x2;
        }
    }
}

// ---------------- FFN kernel: 128 token-rows (16 batches) per block ----------------
#define SM_FFN_FLOATS (128 * PADA)
#define SM_FFN_BYTES  (SM_FFN_FLOATS * 4)

__device__ __forceinline__ void gemm128_tf32(
    const float* __restrict__ sbuf, const float* __restrict__ WB_,
    float C[4][4][4], int mg, int ng, int lane)
{
    const int g = lane >> 2, t = lane & 3;
    const uint2* WB = (const uint2*)WB_;
    const unsigned* sa = (const unsigned*)sbuf;

    #pragma unroll 1
    for (int ks = 0; ks < 16; ks++) {
        uint2 B[4];
        #pragma unroll
        for (int n = 0; n < 4; n++)
            B[n] = __ldg(WB + ((ks * 16 + ng * 4 + n) * 32 + lane));
        #pragma unroll
        for (int m = 0; m < 4; m++) {
            const unsigned* pa = sa + ((mg * 4 + m) * 16 + g) * PADA + ks * 8 + t;
            unsigned A4[4];
            A4[0] = pa[0];
            A4[1] = pa[8 * PADA];
            A4[2] = pa[4];
            A4[3] = pa[8 * PADA + 4];
            #pragma unroll
            for (int n = 0; n < 4; n++)
                mma_tf32(C[m][n], A4, B[n].x, B[n].y);
        }
    }
}

__global__ __launch_bounds__(256, 2) void ffn_kernel(
    const float* __restrict__ ln2_g, const float* __restrict__ ln2_b,
    const float* __restrict__ bf1, const float* __restrict__ bf2,
    float* __restrict__ out)
{
    extern __shared__ float sb[];   // [128][132]
    const int tid = threadIdx.x;
    const int w = tid >> 5, lane = tid & 31;
    const float* xblk = g_x + (size_t)blockIdx.x * 128 * CDIM;

    // ---- LN2 on 128 rows (warp handles 16 rows) ----
    {
        const float4 gv  = __ldg((const float4*)ln2_g + lane);
        const float4 bv2 = __ldg((const float4*)ln2_b + lane);
        for (int i = 0; i < 16; i++) {
            const int row = w * 16 + i;
            float4 xv = __ldg((const float4*)(xblk + row * CDIM) + lane);
            float s1 = xv.x + xv.y + xv.z + xv.w;
            float s2 = xv.x * xv.x + xv.y * xv.y + xv.z * xv.z + xv.w * xv.w;
            s1 = warp_sum(s1);
            s2 = warp_sum(s2);
            float m = s1 * (1.0f / 128.0f);
            float var = s2 * (1.0f / 128.0f) - m * m;
            float rs = rsqrtf(var + LN_EPS);
            uint4 u;
            u.x = f2tf32((xv.x - m) * rs * gv.x + bv2.x);
            u.y = f2tf32((xv.y - m) * rs * gv.y + bv2.y);
            u.z = f2tf32((xv.z - m) * rs * gv.z + bv2.z);
            u.w = f2tf32((xv.w - m) * rs * gv.w + bv2.w);
            *(uint4*)&sb[row * PADA + lane * 4] = u;
        }
    }
    __syncthreads();

    const int mg = w >> 2, ng = w & 3;
    const int g = lane >> 2, t = lane & 3;

    // ---- GEMM: ln @ Wf1 ----
    float C[4][4][4];
    #pragma unroll
    for (int m = 0; m < 4; m++)
        #pragma unroll
        for (int n = 0; n < 4; n++)
            #pragma unroll
            for (int q = 0; q < 4; q++) C[m][n][q] = 0.0f;
    gemm128_tf32(sb, g_Wf1B, C, mg, ng, lane);
    __syncthreads();

    // ---- gelu (exact), round tf32, store to sb ----
    #pragma unroll
    for (int n = 0; n < 4; n++) {
        const int c0 = (ng * 4 + n) * 8 + 2 * t;
        const float b10 = __ldg(bf1 + c0), b11 = __ldg(bf1 + c0 + 1);
        #pragma unroll
        for (int m = 0; m < 4; m++) {
            const int r1 = (mg * 4 + m) * 16 + g;
            float v00 = C[m][n][0] + b10, v01 = C[m][n][1] + b11;
            float v10 = C[m][n][2] + b10, v11 = C[m][n][3] + b11;
            v00 = 0.5f * v00 * (1.0f + erff(v00 * 0.70710678118654752f));
            v01 = 0.5f * v01 * (1.0f + erff(v01 * 0.70710678118654752f));
            v10 = 0.5f * v10 * (1.0f + erff(v10 * 0.70710678118654752f));
            v11 = 0.5f * v11 * (1.0f + erff(v11 * 0.70710678118654752f));
            uint2 u1; u1.x = f2tf32(v00); u1.y = f2tf32(v01);
            uint2 u2; u2.x = f2tf32(v10); u2.y = f2tf32(v11);
            *(uint2*)&sb[r1 * PADA + c0]       = u1;
            *(uint2*)&sb[(r1 + 8) * PADA + c0] = u2;
        }
    }
    __syncthreads();

    // ---- GEMM: f @ Wf2 ; out = x + h ----
    #pragma unroll
    for (int m = 0; m < 4; m++)
        #pragma unroll
        for (int n = 0; n < 4; n++)
            #pragma unroll
            for (int q = 0; q < 4; q++) C[m][n][q] = 0.0f;
    gemm128_tf32(sb, g_Wf2B, C, mg, ng, lane);

    #pragma unroll
    for (int n = 0; n < 4; n++) {
        const int c0 = (ng * 4 + n) * 8 + 2 * t;
        const float b20 = __ldg(bf2 + c0), b21 = __ldg(bf2 + c0 + 1);
        #pragma unroll
        for (int m = 0; m < 4; m++) {
            const int r1 = (mg * 4 + m) * 16 + g;
            const int r2 = r1 + 8;
            const size_t gr = (size_t)blockIdx.x * 128;
            float x00 = __ldg(xblk + r1 * CDIM + c0), x01 = __ldg(xblk + r1 * CDIM + c0 + 1);
            float x10 = __ldg(xblk + r2 * CDIM + c0), x11 = __ldg(xblk + r2 * CDIM + c0 + 1);
            float2 o1 = make_float2(C[m][n][0] + b20 + x00, C[m][n][1] + b21 + x01);
            float2 o2 = make_float2(C[m][n][2] + b20 + x10, C[m][n][3] + b21 + x11);
            *(float2*)&out[(gr + r1) * CDIM + c0] = o1;
            *(float2*)&out[(gr + r2) * CDIM + c0] = o2;
        }
    }
}

// ---------------- launch ----------------
extern "C" void kernel_launch(void* const* d_in, const int* in_sizes, int n_in,
                              void* d_out, int out_size)
{
    const float* query = (const float*)d_in[0];
    const float* tgt   = (const float*)d_in[1];
    const float* ln1_g = (const float*)d_in[2];
    const float* ln1_b = (const float*)d_in[3];
    const float* ln2_g = (const float*)d_in[4];
    const float* ln2_b = (const float*)d_in[5];
    const float* Wq    = (const float*)d_in[6];
    const float* bq    = (const float*)d_in[7];
    const float* Wk    = (const float*)d_in[8];
    const float* Wv    = (const float*)d_in[10];
    const float* bv    = (const float*)d_in[11];
    const float* Wp    = (const float*)d_in[12];
    const float* bp    = (const float*)d_in[13];
    const float* Wf1   = (const float*)d_in[14];
    const float* bf1   = (const float*)d_in[15];
    const float* Wf2   = (const float*)d_in[16];
    const float* bf2   = (const float*)d_in[17];
    float* out = (float*)d_out;

    const int B = in_sizes[1] / (LTOK * CDIM);

    static int attr_done = 0;
    if (!attr_done) {
        cudaFuncSetAttribute(attn_kernel, cudaFuncAttributeMaxDynamicSharedMemorySize, SM_ATTN_BYTES);
        cudaFuncSetAttribute(ffn_kernel,  cudaFuncAttributeMaxDynamicSharedMemorySize, SM_FFN_BYTES);
        attr_done = 1;
    }

    precompute_kernel<<<1, 256>>>(query, ln1_g, ln1_b, Wq, bq, Wk, Wv, Wp, Wf1, Wf2);
    attn_kernel<<<B / 2, 256, SM_ATTN_BYTES>>>(tgt, query, bv, bp);
    ffn_kernel<<<(B * NTOK) / 128, 256, SM_FFN_BYTES>>>(ln2_g, ln2_b, bf1, bf2, out);
}

// round 3
// speedup vs baseline: 3.3923x; 1.7348x over previous
#include <cuda_runtime.h>
#include <cuda_bf16.h>
#include <math.h>

#define CDIM   128
#define LTOK   54
#define NTOK   8
#define LN_EPS 1e-5f
#define MAXB   8192
#define SAW    68        // smem row stride in bf16x2 words (136 bf16) -> conflict-free A frags

// ---------------- device globals ----------------
__device__ float g_x[(size_t)MAXB * NTOK * CDIM];   // fp32 scratch: x after attention+proj
__device__ float g_q[NTOK * CDIM];                  // q vectors (P1 -> P2 not needed, P1 internal)
__device__ float g_Af[CDIM * 64];                   // folded A matrix [k][tok*8+h], fp32
__device__ uint2 g_WcB [8 * 24 * 32];               // combined [A_fold | Wv] bf16 B-frags
__device__ uint2 g_WpB [8 * 16 * 32];               // Wp  bf16 B-frags
__device__ uint2 g_Wf1B[8 * 16 * 32];               // Wf1 bf16 B-frags
__device__ uint2 g_Wf2B[8 * 16 * 32];               // Wf2 bf16 B-frags

// ---------------- helpers ----------------
__device__ __forceinline__ unsigned bfpack(float lo, float hi) {
    __nv_bfloat162 h = __floats2bfloat162_rn(lo, hi);
    return *(unsigned*)&h;
}
__device__ __forceinline__ float2 bfunpack(unsigned u) {
    return __bfloat1622float2(*(__nv_bfloat162*)&u);
}

__device__ __forceinline__ void mma_bf16(float* c, const unsigned* a, unsigned b0, unsigned b1) {
    asm volatile(
        "mma.sync.aligned.m16n8k16.row.col.f32.bf16.bf16.f32 "
        "{%0,%1,%2,%3},{%4,%5,%6,%7},{%8,%9},{%0,%1,%2,%3};"
        : "+f"(c[0]), "+f"(c[1]), "+f"(c[2]), "+f"(c[3])
        : "r"(a[0]), "r"(a[1]), "r"(a[2]), "r"(a[3]), "r"(b0), "r"(b1));
}

__device__ __forceinline__ float warp_sum(float v) {
    v += __shfl_xor_sync(0xffffffffu, v, 16);
    v += __shfl_xor_sync(0xffffffffu, v, 8);
    v += __shfl_xor_sync(0xffffffffu, v, 4);
    v += __shfl_xor_sync(0xffffffffu, v, 2);
    v += __shfl_xor_sync(0xffffffffu, v, 1);
    return v;
}

// ---------------- P1: LN1 -> q -> A fold (single small block) ----------------
__global__ void precompute1_kernel(
    const float* __restrict__ query,
    const float* __restrict__ ln1_g, const float* __restrict__ ln1_b,
    const float* __restrict__ Wq, const float* __restrict__ bq,
    const float* __restrict__ Wk)
{
    __shared__ float s_qn[NTOK * CDIM];
    __shared__ float s_q[NTOK * CDIM];
    const int tid = threadIdx.x;   // 256
    const int warp = tid >> 5, lane = tid & 31;

    if (warp < NTOK) {
        const int r = warp;
        float4 xv = *(const float4*)&query[r * CDIM + lane * 4];
        float s1 = xv.x + xv.y + xv.z + xv.w;
        float s2 = xv.x * xv.x + xv.y * xv.y + xv.z * xv.z + xv.w * xv.w;
        s1 = warp_sum(s1);
        s2 = warp_sum(s2);
        float m = s1 * (1.0f / 128.0f);
        float var = s2 * (1.0f / 128.0f) - m * m;
        float rs = rsqrtf(var + LN_EPS);
        float4 g = *(const float4*)&ln1_g[lane * 4];
        float4 be = *(const float4*)&ln1_b[lane * 4];
        float4 o;
        o.x = (xv.x - m) * rs * g.x + be.x;
        o.y = (xv.y - m) * rs * g.y + be.y;
        o.z = (xv.z - m) * rs * g.z + be.z;
        o.w = (xv.w - m) * rs * g.w + be.w;
        *(float4*)&s_qn[r * CDIM + lane * 4] = o;
    }
    __syncthreads();

    for (int idx = tid; idx < NTOK * CDIM; idx += 256) {
        int t = idx >> 7, o = idx & 127;
        float acc = bq[o];
        for (int c = 0; c < CDIM; c++) acc += s_qn[t * CDIM + c] * Wq[c * CDIM + o];
        s_q[idx] = acc;
    }
    __syncthreads();

    // A_fold[k][tok*8+h] = 0.25 * sum_j q[tok][h*16+j] * Wk[k][h*16+j]
    // (bk contribution is constant per (tok,h) logit column -> cancels in softmax)
    for (int idx = tid; idx < CDIM * 64; idx += 256) {
        int k = idx >> 6, c = idx & 63;
        int tok = c >> 3, h = c & 7;
        float acc = 0.0f;
        #pragma unroll
        for (int j = 0; j < 16; j++)
            acc += s_q[tok * CDIM + h * 16 + j] * Wk[k * CDIM + h * 16 + j];
        g_Af[idx] = 0.25f * acc;
    }
}

// ---------------- P2: pack all weights into bf16 B-fragment order (parallel) ----------------
// total entries: 6144 (Wc) + 3*4096 = 18432 uint2
__global__ void precompute2_kernel(
    const float* __restrict__ Wv,
    const float* __restrict__ Wp,
    const float* __restrict__ Wf1,
    const float* __restrict__ Wf2)
{
    const int gid = blockIdx.x * blockDim.x + threadIdx.x;
    if (gid < 6144) {
        const int lane = gid & 31;
        const int rest = gid >> 5;
        const int nt = rest % 24;
        const int ks = rest / 24;
        const int g = lane >> 2, t = lane & 3;
        const int c = nt * 8 + g;
        const int k0 = ks * 16 + 2 * t;
        float f0, f1, f2, f3;
        if (c < 64) {
            f0 = g_Af[(k0    ) * 64 + c];
            f1 = g_Af[(k0 + 1) * 64 + c];
            f2 = g_Af[(k0 + 8) * 64 + c];
            f3 = g_Af[(k0 + 9) * 64 + c];
        } else {
            const int cc = c - 64;
            f0 = Wv[(k0    ) * CDIM + cc];
            f1 = Wv[(k0 + 1) * CDIM + cc];
            f2 = Wv[(k0 + 8) * CDIM + cc];
            f3 = Wv[(k0 + 9) * CDIM + cc];
        }
        g_WcB[gid] = make_uint2(bfpack(f0, f1), bfpack(f2, f3));
    } else if (gid < 18432) {
        const int r = (gid - 6144) & 4095;
        const int m = (gid - 6144) >> 12;
        const int lane = r & 31;
        const int rest = r >> 5;
        const int nt = rest & 15;
        const int ks = rest >> 4;
        const int g = lane >> 2, t = lane & 3;
        const int c = nt * 8 + g;
        const int k0 = ks * 16 + 2 * t;
        const float* W = (m == 0) ? Wp : (m == 1) ? Wf1 : Wf2;
        uint2 v = make_uint2(
            bfpack(W[k0 * CDIM + c], W[(k0 + 1) * CDIM + c]),
            bfpack(W[(k0 + 8) * CDIM + c], W[(k0 + 9) * CDIM + c]));
        if (m == 0)      g_WpB [r] = v;
        else if (m == 1) g_Wf1B[r] = v;
        else             g_Wf2B[r] = v;
    }
}

// ---------------- attention kernel: 2 batches per block, 512 threads ----------------
// smem (words = 4B):
//   sA  [128][SAW] bf16x2 : tgt, reused for V after GEMM1   -> 8704 words
//   sD  [108][68]  fp32   : dots                            -> 7344 words
//   sAt [16][SAW]  bf16x2 : attention output                -> 1088 words
#define SM_A_WORDS  (128 * SAW)
#define SM_D_WORDS  (108 * 68)
#define SM_AT_WORDS (16 * SAW)
#define SM_ATTN_BYTES ((SM_A_WORDS + SM_D_WORDS + SM_AT_WORDS) * 4)

__global__ __launch_bounds__(512, 1) void attn_kernel(
    const float* __restrict__ tgt,
    const float* __restrict__ query,
    const float* __restrict__ bv,
    const float* __restrict__ bp)
{
    extern __shared__ unsigned smw[];
    unsigned* sA  = smw;
    float*    sD  = (float*)(smw + SM_A_WORDS);
    unsigned* sAt = smw + SM_A_WORDS + SM_D_WORDS;

    const int tid = threadIdx.x;
    const int w = tid >> 5, lane = tid & 31;
    const int g = lane >> 2, t = lane & 3;
    const int b0 = blockIdx.x * 2;

    // ---- stage tgt (2 batches, 108 rows) as bf16 ----
    {
        const float4* gt = (const float4*)(tgt + (size_t)b0 * (LTOK * CDIM));
        for (int i = tid; i < 2 * LTOK * 32; i += 512) {
            const int row = i >> 5, c4 = i & 31;
            float4 v = __ldg(gt + i);
            const int bb = (row >= LTOK) ? 1 : 0;
            const int r = row - bb * LTOK;
            uint2 u = make_uint2(bfpack(v.x, v.y), bfpack(v.z, v.w));
            *(uint2*)&sA[(bb * 64 + r) * SAW + c4 * 2] = u;
        }
    }
    __syncthreads();

    // ---- GEMM1: [128(2x64), 128] @ [128, 192] -> dots(64 cols) | V(128 cols) ----
    {
        const int mg = w >> 3;        // batch
        const int ng = w & 7;         // 3 n-tiles each
        float C[4][3][4];
        #pragma unroll
        for (int m = 0; m < 4; m++)
            #pragma unroll
            for (int n = 0; n < 3; n++)
                #pragma unroll
                for (int q = 0; q < 4; q++) C[m][n][q] = 0.0f;

        #pragma unroll 1
        for (int ks = 0; ks < 8; ks++) {
            uint2 B[3];
            #pragma unroll
            for (int n = 0; n < 3; n++)
                B[n] = __ldg(&g_WcB[(ks * 24 + ng * 3 + n) * 32 + lane]);
            #pragma unroll
            for (int m = 0; m < 4; m++) {
                const unsigned* pa = sA + (mg * 64 + m * 16 + g) * SAW + ks * 8 + t;
                unsigned A4[4];
                A4[0] = pa[0];
                A4[1] = pa[8 * SAW];
                A4[2] = pa[4];
                A4[3] = pa[8 * SAW + 4];
                #pragma unroll
                for (int n = 0; n < 3; n++)
                    mma_bf16(C[m][n], A4, B[n].x, B[n].y);
            }
        }
        __syncthreads();   // all A reads complete before V overwrites sA

        #pragma unroll
        for (int m = 0; m < 4; m++) {
            const int r1 = m * 16 + g;
            #pragma unroll
            for (int n = 0; n < 3; n++) {
                const int nt = ng * 3 + n;
                const int c0 = nt * 8 + 2 * t;
                if (nt < 8) {
                    float* d0 = sD + (mg * LTOK + r1) * 68 + c0;
                    if (r1 < LTOK)     *(float2*)d0            = make_float2(C[m][n][0], C[m][n][1]);
                    if (r1 + 8 < LTOK) *(float2*)(d0 + 8 * 68) = make_float2(C[m][n][2], C[m][n][3]);
                } else {
                    const int wrd = (nt - 8) * 4 + t;   // bf16x2 word within V row
                    unsigned* v0 = sA + (mg * 64 + r1) * SAW + wrd;
                    if (r1 < LTOK)     v0[0]       = bfpack(C[m][n][0], C[m][n][1]);
                    if (r1 + 8 < LTOK) v0[8 * SAW] = bfpack(C[m][n][2], C[m][n][3]);
                }
            }
        }
    }
    __syncthreads();

    // ---- softmax + AV: 128 tasks (2 batches x 8 tok x 8 heads) ----
    if (tid < 128) {
        const int bb = tid >> 6, th = tid & 63;
        const int tok = th >> 3, h = th & 7;
        const int ridx = (tok < 2) ? tok : (tok - 2);
        const int hb = ridx / 3, wb = ridx % 3;
        const int l0 = hb * 27 + wb * 3;
        int ls[9];
        #pragma unroll
        for (int d = 0; d < 9; d++) ls[d] = l0 + (d / 3) * 9 + (d % 3);

        float dv[9];
        float mx = -1e30f;
        #pragma unroll
        for (int d = 0; d < 9; d++) {
            dv[d] = sD[(bb * LTOK + ls[d]) * 68 + th];
            mx = fmaxf(mx, dv[d]);
        }
        float ssum = 0.0f;
        #pragma unroll
        for (int d = 0; d < 9; d++) {
            dv[d] = __expf(dv[d] - mx);
            ssum += dv[d];
        }
        const float inv = 1.0f / ssum;
        float acc[16];
        #pragma unroll
        for (int j = 0; j < 16; j++) acc[j] = 0.0f;
        #pragma unroll
        for (int d = 0; d < 9; d++) {
            const unsigned* vr = sA + (bb * 64 + ls[d]) * SAW + h * 8;
            #pragma unroll
            for (int j = 0; j < 8; j++) {
                float2 vv = bfunpack(vr[j]);
                acc[2 * j]     += dv[d] * vv.x;
                acc[2 * j + 1] += dv[d] * vv.y;
            }
        }
        unsigned* ao = sAt + (bb * 8 + tok) * SAW + h * 8;
        #pragma unroll
        for (int j = 0; j < 8; j++) {
            float bv0 = __ldg(bv + h * 16 + 2 * j);
            float bv1 = __ldg(bv + h * 16 + 2 * j + 1);
            ao[j] = bfpack(acc[2 * j] * inv + bv0, acc[2 * j + 1] * inv + bv1);
        }
    }
    __syncthreads();

    // ---- proj: x = query + attn @ Wp + bp -> g_x (16 warps, 1 n-tile each) ----
    {
        float Cp[4] = {0.f, 0.f, 0.f, 0.f};
        #pragma unroll 1
        for (int ks = 0; ks < 8; ks++) {
            const unsigned* pa = sAt + g * SAW + ks * 8 + t;
            unsigned A4[4];
            A4[0] = pa[0];
            A4[1] = pa[8 * SAW];
            A4[2] = pa[4];
            A4[3] = pa[8 * SAW + 4];
            uint2 b = __ldg(&g_WpB[(ks * 16 + w) * 32 + lane]);
            mma_bf16(Cp, A4, b.x, b.y);
        }
        const int c0 = w * 8 + 2 * t;
        const float bp0 = __ldg(bp + c0), bp1 = __ldg(bp + c0 + 1);
        const float q0 = __ldg(query + g * CDIM + c0);
        const float q1 = __ldg(query + g * CDIM + c0 + 1);
        // row g -> (batch b0, tok g); row g+8 -> (batch b0+1, tok g)
        *(float2*)&g_x[((size_t)b0 * 8 + g) * CDIM + c0] =
            make_float2(Cp[0] + bp0 + q0, Cp[1] + bp1 + q1);
        *(float2*)&g_x[((size_t)(b0 + 1) * 8 + g) * CDIM + c0] =
            make_float2(Cp[2] + bp0 + q0, Cp[3] + bp1 + q1);
    }
}

// ---------------- FFN kernel: 128 token-rows (16 batches) per block, 256 threads ----------------
#define SM_FFN_BYTES (128 * SAW * 4)

__device__ __forceinline__ void gemm128_bf16(
    const unsigned* __restrict__ sbuf, const uint2* __restrict__ WB,
    float C[4][4][4], int mg, int ng, int lane)
{
    const int g = lane >> 2, t = lane & 3;
    #pragma unroll 1
    for (int ks = 0; ks < 8; ks++) {
        uint2 B[4];
        #pragma unroll
        for (int n = 0; n < 4; n++)
            B[n] = __ldg(&WB[(ks * 16 + ng * 4 + n) * 32 + lane]);
        #pragma unroll
        for (int m = 0; m < 4; m++) {
            const unsigned* pa = sbuf + ((mg * 4 + m) * 16 + g) * SAW + ks * 8 + t;
            unsigned A4[4];
            A4[0] = pa[0];
            A4[1] = pa[8 * SAW];
            A4[2] = pa[4];
            A4[3] = pa[8 * SAW + 4];
            #pragma unroll
            for (int n = 0; n < 4; n++)
                mma_bf16(C[m][n], A4, B[n].x, B[n].y);
        }
    }
}

__global__ __launch_bounds__(256, 2) void ffn_kernel(
    const float* __restrict__ ln2_g, const float* __restrict__ ln2_b,
    const float* __restrict__ bf1, const float* __restrict__ bf2,
    float* __restrict__ out)
{
    extern __shared__ unsigned sb[];   // [128][SAW] bf16x2
    const int tid = threadIdx.x;
    const int w = tid >> 5, lane = tid & 31;
    const float* xblk = g_x + (size_t)blockIdx.x * 128 * CDIM;

    // ---- LN2 on 128 rows ----
    {
        const float4 gv  = __ldg((const float4*)ln2_g + lane);
        const float4 bv2 = __ldg((const float4*)ln2_b + lane);
        for (int i = 0; i < 16; i++) {
            const int row = w * 16 + i;
            float4 xv = __ldg((const float4*)(xblk + row * CDIM) + lane);
            float s1 = xv.x + xv.y + xv.z + xv.w;
            float s2 = xv.x * xv.x + xv.y * xv.y + xv.z * xv.z + xv.w * xv.w;
            s1 = warp_sum(s1);
            s2 = warp_sum(s2);
            float m = s1 * (1.0f / 128.0f);
            float var = s2 * (1.0f / 128.0f) - m * m;
            float rs = rsqrtf(var + LN_EPS);
            uint2 u = make_uint2(
                bfpack((xv.x - m) * rs * gv.x + bv2.x, (xv.y - m) * rs * gv.y + bv2.y),
                bfpack((xv.z - m) * rs * gv.z + bv2.z, (xv.w - m) * rs * gv.w + bv2.w));
            *(uint2*)&sb[row * SAW + lane * 2] = u;
        }
    }
    __syncthreads();

    const int mg = w >> 2, ng = w & 3;
    const int g = lane >> 2, t = lane & 3;

    // ---- GEMM: ln @ Wf1 ----
    float C[4][4][4];
    #pragma unroll
    for (int m = 0; m < 4; m++)
        #pragma unroll
        for (int n = 0; n < 4; n++)
            #pragma unroll
            for (int q = 0; q < 4; q++) C[m][n][q] = 0.0f;
    gemm128_bf16(sb, g_Wf1B, C, mg, ng, lane);
    __syncthreads();

    // ---- gelu (exact) -> bf16 -> sb ----
    #pragma unroll
    for (int n = 0; n < 4; n++) {
        const int c0 = (ng * 4 + n) * 8 + 2 * t;
        const int wrd = (ng * 4 + n) * 4 + t;
        const float b10 = __ldg(bf1 + c0), b11 = __ldg(bf1 + c0 + 1);
        #pragma unroll
        for (int m = 0; m < 4; m++) {
            const int r1 = (mg * 4 + m) * 16 + g;
            float v00 = C[m][n][0] + b10, v01 = C[m][n][1] + b11;
            float v10 = C[m][n][2] + b10, v11 = C[m][n][3] + b11;
            v00 = 0.5f * v00 * (1.0f + erff(v00 * 0.70710678118654752f));
            v01 = 0.5f * v01 * (1.0f + erff(v01 * 0.70710678118654752f));
            v10 = 0.5f * v10 * (1.0f + erff(v10 * 0.70710678118654752f));
            v11 = 0.5f * v11 * (1.0f + erff(v11 * 0.70710678118654752f));
            sb[r1 * SAW + wrd]       = bfpack(v00, v01);
            sb[(r1 + 8) * SAW + wrd] = bfpack(v10, v11);
        }
    }
    __syncthreads();

    // ---- GEMM: f @ Wf2 ; out = x + h ----
    #pragma unroll
    for (int m = 0; m < 4; m++)
        #pragma unroll
        for (int n = 0; n < 4; n++)
            #pragma unroll
            for (int q = 0; q < 4; q++) C[m][n][q] = 0.0f;
    gemm128_bf16(sb, g_Wf2B, C, mg, ng, lane);

    #pragma unroll
    for (int n = 0; n < 4; n++) {
        const int c0 = (ng * 4 + n) * 8 + 2 * t;
        const float b20 = __ldg(bf2 + c0), b21 = __ldg(bf2 + c0 + 1);
        #pragma unroll
        for (int m = 0; m < 4; m++) {
            const int r1 = (mg * 4 + m) * 16 + g;
            const int r2 = r1 + 8;
            const size_t gr = (size_t)blockIdx.x * 128;
            float x00 = __ldg(xblk + r1 * CDIM + c0), x01 = __ldg(xblk + r1 * CDIM + c0 + 1);
            float x10 = __ldg(xblk + r2 * CDIM + c0), x11 = __ldg(xblk + r2 * CDIM + c0 + 1);
            *(float2*)&out[(gr + r1) * CDIM + c0] = make_float2(C[m][n][0] + b20 + x00, C[m][n][1] + b21 + x01);
            *(float2*)&out[(gr + r2) * CDIM + c0] = make_float2(C[m][n][2] + b20 + x10, C[m][n][3] + b21 + x11);
        }
    }
}

// ---------------- launch ----------------
extern "C" void kernel_launch(void* const* d_in, const int* in_sizes, int n_in,
                              void* d_out, int out_size)
{
    const float* query = (const float*)d_in[0];
    const float* tgt   = (const float*)d_in[1];
    const float* ln1_g = (const float*)d_in[2];
    const float* ln1_b = (const float*)d_in[3];
    const float* ln2_g = (const float*)d_in[4];
    const float* ln2_b = (const float*)d_in[5];
    const float* Wq    = (const float*)d_in[6];
    const float* bq    = (const float*)d_in[7];
    const float* Wk    = (const float*)d_in[8];
    const float* Wv    = (const float*)d_in[10];
    const float* bv    = (const float*)d_in[11];
    const float* Wp    = (const float*)d_in[12];
    const float* bp    = (const float*)d_in[13];
    const float* Wf1   = (const float*)d_in[14];
    const float* bf1   = (const float*)d_in[15];
    const float* Wf2   = (const float*)d_in[16];
    const float* bf2   = (const float*)d_in[17];
    float* out = (float*)d_out;

    const int B = in_sizes[1] / (LTOK * CDIM);

    cudaFuncSetAttribute(attn_kernel, cudaFuncAttributeMaxDynamicSharedMemorySize, SM_ATTN_BYTES);
    cudaFuncSetAttribute(ffn_kernel,  cudaFuncAttributeMaxDynamicSharedMemorySize, SM_FFN_BYTES);

    precompute1_kernel<<<1, 256>>>(query, ln1_g, ln1_b, Wq, bq, Wk);
    precompute2_kernel<<<72, 256>>>(Wv, Wp, Wf1, Wf2);
    attn_kernel<<<B / 2, 512, SM_ATTN_BYTES>>>(tgt, query, bv, bp);
    ffn_kernel<<<(B * NTOK) / 128, 256, SM_FFN_BYTES>>>(ln2_g, ln2_b, bf1, bf2, out);
}